// round 15
// baseline (speedup 1.0000x reference)
#include <cuda_runtime.h>
#include <math.h>

#define DEG2RAD 0.017453292519943295f
#define CLIP1(v) fminf(fmaxf((v), -1.0f + 1e-5f), 1.0f - 1e-5f)
#define FPA 64          // faces per block in K_a
#define FPB 32          // faces per block in K_b
#define MAXFACES 163840 // >= B*F = 8*20000

// SoA-of-float4 feature scratch (static __device__, no allocation):
// f0 = (Ax,Ay,Az,Bx)  f1 = (By,Bz,Cx,Cy)  f2 = (Cz,a0,a1,a2)  f3 = (nx,ny,nz,area)
__device__ float4 g_f0[MAXFACES];
__device__ float4 g_f1[MAXFACES];
__device__ float4 g_f2[MAXFACES];
__device__ float4 g_f3[MAXFACES];
__device__ float  g_femno[MAXFACES];

__device__ __forceinline__ float4 ld4(const float* p) {
    return *reinterpret_cast<const float4*>(p);
}
__device__ __forceinline__ void fma4(float4& r, float v, const float4& w) {
    r.x = fmaf(v, w.x, r.x);
    r.y = fmaf(v, w.y, r.y);
    r.z = fmaf(v, w.z, r.z);
    r.w = fmaf(v, w.w, r.w);
}
__device__ __forceinline__ void st4s(float* p, const float4& r) {
    __stcs(reinterpret_cast<float4*>(p), r);   // streaming (evict-first) store
}

// ---------------- K_a: const columns + embedded phase 1 ----------------
// Block: 64 faces. Threads 0..63 compute phase-1 features for their face
// (normal-priority stores -> L2-resident for K_b). Every thread with
// c = t&63 < 52 owns one const float4 column (emangle / emfreq, constant per
// batch) and streams it to faces f = (t>>6) + 4k. No barrier needed: the two
// jobs touch disjoint memory; K_b only starts after this kernel completes.
__global__ __launch_bounds__(256, 4) void ka_kernel(
    const float* __restrict__ vertices, const int* __restrict__ faces,
    const float* __restrict__ theta, const float* __restrict__ phi,
    const float* __restrict__ freq,
    const float* __restrict__ W_emangle, const float* __restrict__ b_emangle,
    const float* __restrict__ W_emfreq,  const float* __restrict__ b_emfreq,
    float* __restrict__ out, int V, int F)
{
    const int t     = threadIdx.x;
    const int bi    = blockIdx.y;
    const int face0 = blockIdx.x * FPA;
    const long long gbase = (long long)bi * F + face0;

    // per-batch incidence direction + freq
    const float th = theta[bi] * DEG2RAD;
    const float ph = phi[bi]   * DEG2RAD;
    float sph, cph, sth, cth;
    sincosf(ph, &sph, &cph);
    sincosf(th, &sth, &cth);
    const float incx = sph * cth, incy = sph * sth, incz = cph;

    // ---- phase 1 (threads 0..63) ----
    if (t < FPA && face0 + t < F) {
        const long long g = gbase + t;
        const int* fp = faces + g * 3;
        const int i0 = fp[0], i1 = fp[1], i2 = fp[2];
        const float* vb = vertices + (long long)bi * V * 3;
        const float Ax = vb[3*i0], Ay = vb[3*i0+1], Az = vb[3*i0+2];
        const float Bx = vb[3*i1], By = vb[3*i1+1], Bz = vb[3*i1+2];
        const float Cx = vb[3*i2], Cy = vb[3*i2+1], Cz = vb[3*i2+2];

        const float e0x = Ax-Cx, e0y = Ay-Cy, e0z = Az-Cz;
        const float e1x = Bx-Ax, e1y = By-Ay, e1z = Bz-Az;
        const float e2x = Cx-Bx, e2y = Cy-By, e2z = Cz-Bz;

        const float r0 = 1.0f / fmaxf(sqrtf(e0x*e0x + e0y*e0y + e0z*e0z), 1e-12f);
        const float r1 = 1.0f / fmaxf(sqrtf(e1x*e1x + e1y*e1y + e1z*e1z), 1e-12f);
        const float r2 = 1.0f / fmaxf(sqrtf(e2x*e2x + e2y*e2y + e2z*e2z), 1e-12f);
        const float n0x = e0x*r0, n0y = e0y*r0, n0z = e0z*r0;
        const float n1x = e1x*r1, n1y = e1y*r1, n1z = e1z*r1;
        const float n2x = e2x*r2, n2y = e2y*r2, n2z = e2z*r2;

        const float nd0 = -(n0x*n0z + n1x*n1z + n2x*n2z);
        const float nd1 = -(n0y*n0x + n1y*n1x + n2y*n2x);
        const float nd2 = -(n0z*n0y + n1z*n1y + n2z*n2y);
        const float a0 = acosf(CLIP1(nd0));
        const float a1 = acosf(CLIP1(nd1));
        const float a2 = acosf(CLIP1(nd2));

        const float crx = e0y*e1z - e0z*e1y;
        const float cry = e0z*e1x - e0x*e1z;
        const float crz = e0x*e1y - e0y*e1x;
        const float cn = sqrtf(crx*crx + cry*cry + crz*crz);
        const float ci = 1.0f / fmaxf(cn, 1e-12f);
        const float nx = crx*ci, ny = cry*ci, nz = crz*ci;
        const float area = 0.5f * cn;

        float ix = incx, iy = incy, iz = incz;
        const float ii = 1.0f / fmaxf(sqrtf(ix*ix + iy*iy + iz*iz), 1e-12f);
        ix *= ii; iy *= ii; iz *= ii;
        const float emno = acosf(CLIP1(-(nx*ix + ny*iy + nz*iz)));

        g_f0[g] = make_float4(Ax, Ay, Az, Bx);
        g_f1[g] = make_float4(By, Bz, Cx, Cy);
        g_f2[g] = make_float4(Cz, a0, a1, a2);
        g_f3[g] = make_float4(nx, ny, nz, area);
        g_femno[g] = emno;
    }

    // ---- const-column streaming ----
    const int c  = t & 63;    // column group 0..51 valid
    const int fo = t >> 6;    // face phase 0..3
    if (c < 52) {
        float4 val;
        int off;
        if (c < 48) {                         // emangle cols [832,1024)
            const int l = 4 * c;
            const float4 w0 = ld4(W_emangle + l);
            const float4 w1 = ld4(W_emangle + 192 + l);
            const float4 w2 = ld4(W_emangle + 384 + l);
            val = ld4(b_emangle + l);
            val.x += incx*w0.x + incy*w1.x + incz*w2.x;
            val.y += incx*w0.y + incy*w1.y + incz*w2.y;
            val.z += incx*w0.z + incy*w1.z + incz*w2.z;
            val.w += incx*w0.w + incy*w1.w + incz*w2.w;
            off = 832 + l;
        } else {                              // emfreq cols [1040,1056)
            const int l = 4 * (c - 48);
            const float4 wf = ld4(W_emfreq + l);
            const float freq_log = (log10f(freq[bi]) + 1.0f) * 0.5f;
            val = ld4(b_emfreq + l);
            val.x = fmaf(freq_log, wf.x, val.x);
            val.y = fmaf(freq_log, wf.y, val.y);
            val.z = fmaf(freq_log, wf.z, val.z);
            val.w = fmaf(freq_log, wf.w, val.w);
            off = 1040 + l;
        }
        const int nf = min(FPA, F - face0);
        float* op = out + (gbase + fo) * 1056 + off;
        for (int f = fo; f < nf; f += 4, op += 4 * 1056)
            st4s(op, val);
    }
}

// ---------------- K_b: feature-dependent columns, barrier-free ----------------
// Warp-aligned segment map (block = 256 threads, 32 faces):
//   t [0,144)   : coor dot9,  c0 = 4t          (warps 0-4; warp4 lanes 16-31 idle)
//   t [160,172) : angle dot3                    (warp 5, lanes 12-31 idle)
//   t [192,240) : normal dot3                   (warp 6 full + warp 7 lanes 0-15)
//   t [240,244) : area dot1                     (warp 7)
//   t [244,248) : emnoangle dot1, cols 1024-1039(warp 7)
__global__ __launch_bounds__(256, 4) void kb_kernel(
    const float* __restrict__ W_angle,     const float* __restrict__ b_angle,
    const float* __restrict__ W_area,      const float* __restrict__ b_area,
    const float* __restrict__ W_normal,    const float* __restrict__ b_normal,
    const float* __restrict__ W_emnoangle, const float* __restrict__ b_emnoangle,
    const float* __restrict__ W_coor,      const float* __restrict__ b_coor,
    float* __restrict__ out, int F)
{
    const int t     = threadIdx.x;
    const int bi    = blockIdx.y;
    const int face0 = blockIdx.x * FPB;
    const int nf    = min(FPB, F - face0);
    const long long gbase = (long long)bi * F + face0;

    if (t < 144) {                                    // ---- e_coor: dot9 ----
        const int c0 = 4 * t;
        float4 w0 = ld4(W_coor + 0*576 + c0), w1 = ld4(W_coor + 1*576 + c0);
        float4 w2 = ld4(W_coor + 2*576 + c0), w3 = ld4(W_coor + 3*576 + c0);
        float4 w4 = ld4(W_coor + 4*576 + c0), w5 = ld4(W_coor + 5*576 + c0);
        float4 w6 = ld4(W_coor + 6*576 + c0), w7 = ld4(W_coor + 7*576 + c0);
        float4 w8 = ld4(W_coor + 8*576 + c0);
        const float4 base = ld4(b_coor + c0);
        float* op = out + gbase * 1056 + c0;
        #pragma unroll 2
        for (int f = 0; f < nf; f++, op += 1056) {
            const float4 p0 = g_f0[gbase + f];
            const float4 p1 = g_f1[gbase + f];
            const float p8 = g_f2[gbase + f].x;
            float4 r = base;
            fma4(r, p0.x, w0); fma4(r, p0.y, w1); fma4(r, p0.z, w2);
            fma4(r, p0.w, w3); fma4(r, p1.x, w4); fma4(r, p1.y, w5);
            fma4(r, p1.z, w6); fma4(r, p1.w, w7); fma4(r, p8,   w8);
            st4s(op, r);
        }
    } else if (t >= 160 && t < 172) {                 // ---- e_angle: dot3 ----
        const int l = 4 * (t - 160);
        float4 w0 = ld4(W_angle + l), w1 = ld4(W_angle + 48 + l), w2 = ld4(W_angle + 96 + l);
        const float4 base = ld4(b_angle + l);
        float* op = out + gbase * 1056 + 576 + l;
        #pragma unroll 4
        for (int f = 0; f < nf; f++, op += 1056) {
            const float4 p = g_f2[gbase + f];          // (Cz,a0,a1,a2)
            float4 r = base;
            fma4(r, p.y, w0); fma4(r, p.z, w1); fma4(r, p.w, w2);
            st4s(op, r);
        }
    } else if (t >= 192 && t < 240) {                 // ---- e_normal: dot3 ----
        const int l = 4 * (t - 192);
        float4 w0 = ld4(W_normal + l), w1 = ld4(W_normal + 192 + l), w2 = ld4(W_normal + 384 + l);
        const float4 base = ld4(b_normal + l);
        float* op = out + gbase * 1056 + 624 + l;
        #pragma unroll 4
        for (int f = 0; f < nf; f++, op += 1056) {
            const float4 p = g_f3[gbase + f];          // (nx,ny,nz,area)
            float4 r = base;
            fma4(r, p.x, w0); fma4(r, p.y, w1); fma4(r, p.z, w2);
            st4s(op, r);
        }
    } else if (t >= 240 && t < 244) {                 // ---- e_area: dot1 ----
        const int l = 4 * (t - 240);
        float4 w0 = ld4(W_area + l);
        const float4 base = ld4(b_area + l);
        float* op = out + gbase * 1056 + 816 + l;
        #pragma unroll 4
        for (int f = 0; f < nf; f++, op += 1056) {
            float4 r = base;
            fma4(r, g_f3[gbase + f].w, w0);
            st4s(op, r);
        }
    } else if (t >= 244 && t < 248) {                 // ---- e_emnoangle: dot1 ----
        const int l = 4 * (t - 244);
        float4 w0 = ld4(W_emnoangle + l);
        const float4 base = ld4(b_emnoangle + l);
        float* op = out + gbase * 1056 + 1024 + l;
        #pragma unroll 4
        for (int f = 0; f < nf; f++, op += 1056) {
            float4 r = base;
            fma4(r, g_femno[gbase + f], w0);
            st4s(op, r);
        }
    }
}

extern "C" void kernel_launch(void* const* d_in, const int* in_sizes, int n_in,
                              void* d_out, int out_size) {
    const float* vertices     = (const float*)d_in[0];
    const int*   faces        = (const int*)  d_in[1];
    const float* theta        = (const float*)d_in[2];
    const float* phi          = (const float*)d_in[3];
    const float* freq         = (const float*)d_in[4];
    const float* W_angle      = (const float*)d_in[5];
    const float* b_angle      = (const float*)d_in[6];
    const float* W_area       = (const float*)d_in[7];
    const float* b_area       = (const float*)d_in[8];
    const float* W_normal     = (const float*)d_in[9];
    const float* b_normal     = (const float*)d_in[10];
    const float* W_emnoangle  = (const float*)d_in[11];
    const float* b_emnoangle  = (const float*)d_in[12];
    const float* W_emangle    = (const float*)d_in[13];
    const float* b_emangle    = (const float*)d_in[14];
    const float* W_emfreq     = (const float*)d_in[15];
    const float* b_emfreq     = (const float*)d_in[16];
    const float* W_coor       = (const float*)d_in[17];
    const float* b_coor       = (const float*)d_in[18];
    float* out = (float*)d_out;

    const int B = in_sizes[2];
    const int F = in_sizes[1] / (3 * B);
    const int V = in_sizes[0] / (3 * B);

    dim3 grid_a((F + FPA - 1) / FPA, B);
    ka_kernel<<<grid_a, 256>>>(
        vertices, faces, theta, phi, freq,
        W_emangle, b_emangle, W_emfreq, b_emfreq,
        out, V, F);

    dim3 grid_b((F + FPB - 1) / FPB, B);
    kb_kernel<<<grid_b, 256>>>(
        W_angle, b_angle, W_area, b_area, W_normal, b_normal,
        W_emnoangle, b_emnoangle, W_coor, b_coor,
        out, F);
}